// round 8
// baseline (speedup 1.0000x reference)
#include <cuda_runtime.h>
#include <cuda_bf16.h>
#include <cstdint>

#define C_DIM 512
#define S_DIM 4096
#define NH 8
#define HD 64

// Scratch (allocation-free rule: static __device__ globals)
__device__ __nv_bfloat16 g_xb[2 * S_DIM * C_DIM];    // x, token-major [n,s,c] bf16
__device__ __nv_bfloat16 g_Wb[4 * C_DIM * C_DIM];    // Wq,Wk,Wv,Wo bf16 [o][k]
__device__ __nv_bfloat16 g_Qb[2 * NH * S_DIM * HD];  // [n,h,s,d] bf16, 0.125*log2e folded
__device__ __nv_bfloat16 g_Kb[2 * NH * S_DIM * HD];  // [n,h,s,d] bf16
__device__ __nv_bfloat16 g_V [2 * C_DIM * S_DIM];    // [n,h,d,s] bf16
__device__ __nv_bfloat16 g_Ab[2 * S_DIM * C_DIM];    // attn out, token-major [n,s,c] bf16

// ---------------------------------------------------------------------------
// helpers
// ---------------------------------------------------------------------------
__device__ __forceinline__ float ex2f(float x) {
    float y;
    asm("ex2.approx.ftz.f32 %0, %1;" : "=f"(y) : "f"(x));
    return y;
}

__device__ __forceinline__ uint32_t pack_bf16(float lo, float hi) {
    uint32_t r;
    asm("cvt.rn.bf16x2.f32 %0, %1, %2;" : "=r"(r) : "f"(hi), "f"(lo));
    return r;
}

__device__ __forceinline__ void mma_bf16(float* d, uint32_t a0, uint32_t a1,
                                         uint32_t a2, uint32_t a3,
                                         uint32_t b0, uint32_t b1) {
    asm volatile(
        "mma.sync.aligned.m16n8k16.row.col.f32.bf16.bf16.f32 "
        "{%0,%1,%2,%3}, {%4,%5,%6,%7}, {%8,%9}, {%0,%1,%2,%3};"
        : "+f"(d[0]), "+f"(d[1]), "+f"(d[2]), "+f"(d[3])
        : "r"(a0), "r"(a1), "r"(a2), "r"(a3), "r"(b0), "r"(b1));
}

__device__ __forceinline__ void cp16(void* smem, const void* gmem) {
    uint32_t s = (uint32_t)__cvta_generic_to_shared(smem);
    asm volatile("cp.async.cg.shared.global [%0], [%1], 16;" :: "r"(s), "l"(gmem));
}
#define CP_COMMIT() asm volatile("cp.async.commit_group;")
#define CP_WAIT1()  asm volatile("cp.async.wait_group 1;")

// ---------------------------------------------------------------------------
// Prepass 1: x [n,c,s] f32 -> g_xb [n,s,c] bf16 (smem tile transpose)
// grid (S/32, C/32, 2), block (32,8)
// ---------------------------------------------------------------------------
__global__ void conv_x_kernel(const float* __restrict__ x)
{
    __shared__ float tile[32][33];
    const int s0 = blockIdx.x * 32, c0 = blockIdx.y * 32, n = blockIdx.z;
    const int tx = threadIdx.x, ty = threadIdx.y;

    #pragma unroll
    for (int i = ty; i < 32; i += 8)
        tile[i][tx] = x[((size_t)(n * C_DIM + c0 + i)) * S_DIM + s0 + tx];
    __syncthreads();
    #pragma unroll
    for (int i = ty; i < 32; i += 8)
        g_xb[((size_t)(n * S_DIM + s0 + i)) * C_DIM + c0 + tx] =
            __float2bfloat16(tile[tx][i]);
}

// ---------------------------------------------------------------------------
// Prepass 2: weights f32 -> bf16 (layout preserved [o][k])
// grid (256, 4), block 256; each thread converts one float4.
// ---------------------------------------------------------------------------
__global__ void conv_w_kernel(const float* __restrict__ Wq, const float* __restrict__ Wk,
                              const float* __restrict__ Wv, const float* __restrict__ Wo)
{
    const float* src[4] = {Wq, Wk, Wv, Wo};
    const int which = blockIdx.y;
    const int idx = blockIdx.x * 256 + threadIdx.x;   // float4 index
    float4 v = *(const float4*)&src[which][idx * 4];
    uint2 p;
    p.x = pack_bf16(v.x, v.y);
    p.y = pack_bf16(v.z, v.w);
    *(uint2*)&g_Wb[(size_t)which * C_DIM * C_DIM + idx * 4] = p;
}

// ---------------------------------------------------------------------------
// bf16 GEMM tile body, cp.async double-buffered.
// Block 256 thr (8 warps). Tile M=128 (rows of A/out), N=64 (tokens), K chunk 32.
// A: weights bf16 [M,K] k-contig. B: activations bf16 [token][k] k-contig (stride C_DIM).
// acc[ns][0..3]: rows {w*16+qr, +8} x cols {s0+ns*8+2qc, +1}.
// ---------------------------------------------------------------------------
struct GemmSmemB {
    __nv_bfloat16 Ws[2][128][40];   // pad 40 -> conflict-free u32 frag loads
    __nv_bfloat16 Bs[2][64][40];
};

__device__ __forceinline__ void gemm_bf16_pipe(
    GemmSmemB& sm, const __nv_bfloat16* __restrict__ A_gm,
    const __nv_bfloat16* __restrict__ B_gm,
    int o0, int s0, float acc[8][4], int t)
{
    const int lane = t & 31;
    const int w    = t >> 5;
    const int qr   = lane >> 2;
    const int qc   = lane & 3;
    const int row0 = w * 16 + qr;

    auto issue = [&](int ch, int st) {
        const int k0 = ch * 32;
        #pragma unroll
        for (int it = 0; it < 2; it++) {
            int e = t + 256 * it;
            int r = e >> 2, c8 = (e & 3) * 8;
            cp16(&sm.Ws[st][r][c8], A_gm + (size_t)(o0 + r) * C_DIM + k0 + c8);
        }
        {
            int r = t >> 2, c8 = (t & 3) * 8;
            cp16(&sm.Bs[st][r][c8], B_gm + (size_t)(s0 + r) * C_DIM + k0 + c8);
        }
    };

    issue(0, 0); CP_COMMIT();
    issue(1, 1); CP_COMMIT();

    for (int ch = 0; ch < 16; ch++) {
        const int st = ch & 1;
        CP_WAIT1();
        __syncthreads();

        #pragma unroll
        for (int ks = 0; ks < 2; ks++) {
            int c = ks * 16 + 2 * qc;
            uint32_t a0 = *(const uint32_t*)&sm.Ws[st][row0    ][c];
            uint32_t a1 = *(const uint32_t*)&sm.Ws[st][row0 + 8][c];
            uint32_t a2 = *(const uint32_t*)&sm.Ws[st][row0    ][c + 8];
            uint32_t a3 = *(const uint32_t*)&sm.Ws[st][row0 + 8][c + 8];
            #pragma unroll
            for (int ns = 0; ns < 8; ns++) {
                uint32_t b0 = *(const uint32_t*)&sm.Bs[st][ns*8 + qr][c];
                uint32_t b1 = *(const uint32_t*)&sm.Bs[st][ns*8 + qr][c + 8];
                mma_bf16(acc[ns], a0, a1, a2, a3, b0, b1);
            }
        }

        __syncthreads();
        if (ch + 2 < 16) issue(ch + 2, st);
        CP_COMMIT();
    }
}

// ---------------------------------------------------------------------------
// QKV projection: grid (S/64, C/128, 6), block 256.
// ---------------------------------------------------------------------------
__global__ __launch_bounds__(256) void proj_kernel(
    const float* __restrict__ bq, const float* __restrict__ bk,
    const float* __restrict__ bv)
{
    __shared__ GemmSmemB sm;

    const int z = blockIdx.z;
    const int n = z / 3, which = z % 3;
    const __nv_bfloat16* W = g_Wb + (size_t)which * C_DIM * C_DIM;
    const float* bias = (which == 0) ? bq : (which == 1) ? bk : bv;

    const int o0 = blockIdx.y * 128;
    const int s0 = blockIdx.x * 64;
    const __nv_bfloat16* xb = g_xb + (size_t)n * S_DIM * C_DIM;

    const int t    = threadIdx.x;
    const int lane = t & 31;
    const int w    = t >> 5;
    const int qr   = lane >> 2;
    const int qc   = lane & 3;

    float acc[8][4];
    #pragma unroll
    for (int ns = 0; ns < 8; ns++)
        #pragma unroll
        for (int j = 0; j < 4; j++) acc[ns][j] = 0.f;

    gemm_bf16_pipe(sm, W, xb, o0, s0, acc, t);

    const int r0 = o0 + w * 16 + qr;
    const int r1 = r0 + 8;
    const float bi0 = bias[r0], bi1 = bias[r1];

    if (which == 2) {
        // V -> bf16, d-major [n,h,d,s]
        #pragma unroll
        for (int ns = 0; ns < 8; ns++) {
            int col = s0 + ns * 8 + 2 * qc;
            *(uint32_t*)&g_V[(size_t)(n * C_DIM + r0) * S_DIM + col] =
                pack_bf16(acc[ns][0] + bi0, acc[ns][1] + bi0);
            *(uint32_t*)&g_V[(size_t)(n * C_DIM + r1) * S_DIM + col] =
                pack_bf16(acc[ns][2] + bi1, acc[ns][3] + bi1);
        }
    } else {
        __nv_bfloat16* outb = (which == 0) ? g_Qb : g_Kb;
        const float mult = (which == 0) ? 0.125f * 1.4426950408889634f : 1.0f;
        const int h0 = r0 >> 6, d0 = r0 & 63;
        const int h1 = r1 >> 6, d1 = r1 & 63;
        #pragma unroll
        for (int ns = 0; ns < 8; ns++) {
            int col = s0 + ns * 8 + 2 * qc;
            size_t b0i = ((size_t)(n * NH + h0) * S_DIM + col) * HD + d0;
            size_t b1i = ((size_t)(n * NH + h1) * S_DIM + col) * HD + d1;
            outb[b0i]      = __float2bfloat16((acc[ns][0] + bi0) * mult);
            outb[b0i + HD] = __float2bfloat16((acc[ns][1] + bi0) * mult);
            outb[b1i]      = __float2bfloat16((acc[ns][2] + bi1) * mult);
            outb[b1i + HD] = __float2bfloat16((acc[ns][3] + bi1) * mult);
        }
    }
}

// ---------------------------------------------------------------------------
// Flash attention: all-bf16 MMA, cp.async double-buffered K/V (verified R5).
// Output now bf16 token-major [n,s,c]. Block 256, grid (S/128, 16).
// ---------------------------------------------------------------------------
__global__ __launch_bounds__(256) void attn_kernel()
{
    __shared__ __nv_bfloat16 Ks[2][64][72];   // [stage][key][d]
    __shared__ __nv_bfloat16 Vs[2][64][72];   // [stage][d][key]

    const int g  = blockIdx.y;                // n*8 + h
    const int q0 = blockIdx.x * 128;
    const __nv_bfloat16* Qg = g_Qb + (size_t)g * S_DIM * HD;
    const __nv_bfloat16* Kg = g_Kb + (size_t)g * S_DIM * HD;
    const __nv_bfloat16* Vg = g_V  + (size_t)g * HD * S_DIM;

    const int t    = threadIdx.x;
    const int w    = t >> 5;
    const int lane = t & 31;
    const int qr   = lane >> 2;
    const int qc   = lane & 3;
    const int row0 = q0 + w * 16 + qr;

    auto issue = [&](int kt, int st) {
        const int k0 = kt * 64;
        #pragma unroll
        for (int it = 0; it < 2; it++) {
            int e = t + 256 * it;
            int r = e >> 3, c8 = (e & 7) * 8;
            cp16(&Ks[st][r][c8], Kg + (size_t)(k0 + r) * HD + c8);
        }
        #pragma unroll
        for (int it = 0; it < 2; it++) {
            int e = t + 256 * it;
            int r = e >> 3, c8 = (e & 7) * 8;
            cp16(&Vs[st][r][c8], Vg + (size_t)r * S_DIM + k0 + c8);
        }
    };

    issue(0, 0); CP_COMMIT();
    issue(1, 1); CP_COMMIT();

    uint32_t qa[4][4];
    #pragma unroll
    for (int ks = 0; ks < 4; ks++) {
        int c = ks * 16 + 2 * qc;
        qa[ks][0] = *(const uint32_t*)&Qg[(size_t)row0       * HD + c];
        qa[ks][1] = *(const uint32_t*)&Qg[(size_t)(row0 + 8) * HD + c];
        qa[ks][2] = *(const uint32_t*)&Qg[(size_t)row0       * HD + c + 8];
        qa[ks][3] = *(const uint32_t*)&Qg[(size_t)(row0 + 8) * HD + c + 8];
    }

    float o_[8][4];
    #pragma unroll
    for (int ns = 0; ns < 8; ns++)
        #pragma unroll
        for (int j = 0; j < 4; j++) o_[ns][j] = 0.f;
    float m0 = -1e30f, m1 = -1e30f, l0 = 0.f, l1 = 0.f;

    for (int kt = 0; kt < 64; kt++) {
        const int st = kt & 1;
        CP_WAIT1();
        __syncthreads();

        float s_[8][4];
        #pragma unroll
        for (int ns = 0; ns < 8; ns++)
            #pragma unroll
            for (int j = 0; j < 4; j++) s_[ns][j] = 0.f;

        #pragma unroll
        for (int ks = 0; ks < 4; ks++) {
            #pragma unroll
            for (int ns = 0; ns < 8; ns++) {
                uint32_t b0 = *(const uint32_t*)&Ks[st][ns*8 + qr][ks*16 + 2*qc];
                uint32_t b1 = *(const uint32_t*)&Ks[st][ns*8 + qr][ks*16 + 2*qc + 8];
                mma_bf16(s_[ns], qa[ks][0], qa[ks][1], qa[ks][2], qa[ks][3], b0, b1);
            }
        }

        float mt0 = -1e30f, mt1 = -1e30f;
        #pragma unroll
        for (int ns = 0; ns < 8; ns++) {
            mt0 = fmaxf(mt0, fmaxf(s_[ns][0], s_[ns][1]));
            mt1 = fmaxf(mt1, fmaxf(s_[ns][2], s_[ns][3]));
        }
        mt0 = fmaxf(mt0, __shfl_xor_sync(0xffffffffu, mt0, 1));
        mt0 = fmaxf(mt0, __shfl_xor_sync(0xffffffffu, mt0, 2));
        mt1 = fmaxf(mt1, __shfl_xor_sync(0xffffffffu, mt1, 1));
        mt1 = fmaxf(mt1, __shfl_xor_sync(0xffffffffu, mt1, 2));

        float mn0 = fmaxf(m0, mt0), mn1 = fmaxf(m1, mt1);
        float corr0 = ex2f(m0 - mn0), corr1 = ex2f(m1 - mn1);
        m0 = mn0; m1 = mn1;

        float ls0 = 0.f, ls1 = 0.f;
        #pragma unroll
        for (int ns = 0; ns < 8; ns++) {
            s_[ns][0] = ex2f(s_[ns][0] - mn0);
            s_[ns][1] = ex2f(s_[ns][1] - mn0);
            s_[ns][2] = ex2f(s_[ns][2] - mn1);
            s_[ns][3] = ex2f(s_[ns][3] - mn1);
            ls0 += s_[ns][0] + s_[ns][1];
            ls1 += s_[ns][2] + s_[ns][3];
        }
        ls0 += __shfl_xor_sync(0xffffffffu, ls0, 1);
        ls0 += __shfl_xor_sync(0xffffffffu, ls0, 2);
        ls1 += __shfl_xor_sync(0xffffffffu, ls1, 1);
        ls1 += __shfl_xor_sync(0xffffffffu, ls1, 2);
        l0 = l0 * corr0 + ls0;
        l1 = l1 * corr1 + ls1;

        #pragma unroll
        for (int ns = 0; ns < 8; ns++) {
            o_[ns][0] *= corr0; o_[ns][1] *= corr0;
            o_[ns][2] *= corr1; o_[ns][3] *= corr1;
        }

        uint32_t pk[8][2];
        #pragma unroll
        for (int ns = 0; ns < 8; ns++) {
            pk[ns][0] = pack_bf16(s_[ns][0], s_[ns][1]);
            pk[ns][1] = pack_bf16(s_[ns][2], s_[ns][3]);
        }

        #pragma unroll
        for (int ks = 0; ks < 4; ks++) {
            uint32_t a0 = pk[2*ks][0],   a1 = pk[2*ks][1];
            uint32_t a2 = pk[2*ks+1][0], a3 = pk[2*ks+1][1];
            #pragma unroll
            for (int ns = 0; ns < 8; ns++) {
                uint32_t b0 = *(const uint32_t*)&Vs[st][ns*8 + qr][ks*16 + 2*qc];
                uint32_t b1 = *(const uint32_t*)&Vs[st][ns*8 + qr][ks*16 + 2*qc + 8];
                mma_bf16(o_[ns], a0, a1, a2, a3, b0, b1);
            }
        }

        __syncthreads();
        if (kt + 2 < 64) issue(kt + 2, st);
        CP_COMMIT();
    }

    // normalize + write bf16 token-major [n,s,c], c = h*64 + d
    const int n = g >> 3, h = g & 7;
    float inv0 = 1.0f / l0, inv1 = 1.0f / l1;
    #pragma unroll
    for (int ns = 0; ns < 8; ns++) {
        int d = ns * 8 + 2 * qc;
        size_t base = ((size_t)(n * S_DIM + row0)) * C_DIM + h * HD + d;
        *(uint32_t*)&g_Ab[base] = pack_bf16(o_[ns][0] * inv0, o_[ns][1] * inv0);
        *(uint32_t*)&g_Ab[base + (size_t)8 * C_DIM] =
            pack_bf16(o_[ns][2] * inv1, o_[ns][3] * inv1);
    }
}

// ---------------------------------------------------------------------------
// Output projection + residual: grid (S/64, C/128, 2), block 256.
// ---------------------------------------------------------------------------
__global__ __launch_bounds__(256) void oproj_kernel(
    const float* __restrict__ x, const float* __restrict__ bo,
    const float* __restrict__ gamma, float* __restrict__ out)
{
    __shared__ GemmSmemB sm;

    const int n  = blockIdx.z;
    const int o0 = blockIdx.y * 128, s0 = blockIdx.x * 64;
    const __nv_bfloat16* Wo = g_Wb + (size_t)3 * C_DIM * C_DIM;
    const __nv_bfloat16* Bg = g_Ab + (size_t)n * S_DIM * C_DIM;

    const int t    = threadIdx.x;
    const int lane = t & 31;
    const int w    = t >> 5;
    const int qr   = lane >> 2;
    const int qc   = lane & 3;

    float acc[8][4];
    #pragma unroll
    for (int ns = 0; ns < 8; ns++)
        #pragma unroll
        for (int j = 0; j < 4; j++) acc[ns][j] = 0.f;

    gemm_bf16_pipe(sm, Wo, Bg, o0, s0, acc, t);

    const float gam = gamma[0];
    const int r0 = o0 + w * 16 + qr;
    const int r1 = r0 + 8;
    const float bi0 = bo[r0], bi1 = bo[r1];

    #pragma unroll
    for (int ns = 0; ns < 8; ns++) {
        int col = s0 + ns * 8 + 2 * qc;
        size_t i0 = (size_t)(n * C_DIM + r0) * S_DIM + col;
        size_t i1 = (size_t)(n * C_DIM + r1) * S_DIM + col;
        float2 x0 = *(const float2*)&x[i0];
        float2 x1 = *(const float2*)&x[i1];
        float2 v0 = { gam * (acc[ns][0] + bi0) + x0.x,
                      gam * (acc[ns][1] + bi0) + x0.y };
        float2 v1 = { gam * (acc[ns][2] + bi1) + x1.x,
                      gam * (acc[ns][3] + bi1) + x1.y };
        *(float2*)&out[i0] = v0;
        *(float2*)&out[i1] = v1;
    }
}

// ---------------------------------------------------------------------------
extern "C" void kernel_launch(void* const* d_in, const int* in_sizes, int n_in,
                              void* d_out, int out_size)
{
    const float* x     = (const float*)d_in[0];
    const float* Wq    = (const float*)d_in[1];
    const float* bq    = (const float*)d_in[2];
    const float* Wk    = (const float*)d_in[3];
    const float* bk    = (const float*)d_in[4];
    const float* Wv    = (const float*)d_in[5];
    const float* bv    = (const float*)d_in[6];
    const float* Wo    = (const float*)d_in[7];
    const float* bo    = (const float*)d_in[8];
    const float* gamma = (const float*)d_in[9];
    float* out = (float*)d_out;

    dim3 gcx(S_DIM / 32, C_DIM / 32, 2);
    conv_x_kernel<<<gcx, dim3(32, 8)>>>(x);
    conv_w_kernel<<<dim3(256, 4), 256>>>(Wq, Wk, Wv, Wo);

    dim3 gproj(S_DIM / 64, C_DIM / 128, 2 * 3);
    proj_kernel<<<gproj, 256>>>(bq, bk, bv);

    dim3 gattn(S_DIM / 128, 16);
    attn_kernel<<<gattn, 256>>>();

    dim3 gout(S_DIM / 64, C_DIM / 128, 2);
    oproj_kernel<<<gout, 256>>>(x, bo, gamma, out);
}